// round 1
// baseline (speedup 1.0000x reference)
#include <cuda_runtime.h>
#include <math.h>

#define BATCH 1024
#define DIM   128
#define N0    25
#define N1    10
#define NPB   250   // N0*N1 leaf rows per batch element

// Scratch: concat vector per batch element: [s1_mean (0..127) | s2_mean (128..255)]
__device__ float g_cat[BATCH * 256];

// ---------------------------------------------------------------------------
// Kernel 1: gather + reduce. One block per batch element.
// 256 threads: d = tid&127 (embedding dim), g = tid>>7 (row-split group).
// ---------------------------------------------------------------------------
__global__ __launch_bounds__(256) void gather_reduce_kernel(
    const float* __restrict__ embed,
    const int*   __restrict__ idx1,
    const int*   __restrict__ idx2)
{
    __shared__ int   sIdx2[NPB];
    __shared__ int   sIdx1[N0];
    __shared__ float red[512];

    const int b   = blockIdx.x;
    const int tid = threadIdx.x;
    const int d   = tid & 127;
    const int g   = tid >> 7;

    // Stage indices in shared
    if (tid < NPB) sIdx2[tid] = idx2[b * NPB + tid];
    if (tid < N0)  sIdx1[tid] = idx1[b * N0 + tid];
    __syncthreads();

    const float* E = embed + d;

    // Sum of 125 leaf rows per group (5-wide for MLP)
    float acc2 = 0.f;
    const int base = g * 125;
    for (int r = 0; r < 125; r += 5) {
        float v0 = __ldg(E + (size_t)sIdx2[base + r    ] * DIM);
        float v1 = __ldg(E + (size_t)sIdx2[base + r + 1] * DIM);
        float v2 = __ldg(E + (size_t)sIdx2[base + r + 2] * DIM);
        float v3 = __ldg(E + (size_t)sIdx2[base + r + 3] * DIM);
        float v4 = __ldg(E + (size_t)sIdx2[base + r + 4] * DIM);
        acc2 += (v0 + v1) + (v2 + v3) + v4;
    }

    // Sum of first-hop rows, split by parity across groups
    float acc1 = 0.f;
    for (int r = g; r < N0; r += 2)
        acc1 += __ldg(E + (size_t)sIdx1[r] * DIM);

    red[tid]       = acc2;
    red[256 + tid] = acc1;
    __syncthreads();

    float outv;
    if (tid < 128) {
        // s1 mean (first-hop): dims 0..127 of concat
        outv = (red[256 + tid] + red[384 + tid]) * (1.0f / 25.0f);
    } else {
        // s2 mean (leaf): dims 128..255 of concat
        const int dd = tid - 128;
        outv = (red[dd] + red[128 + dd]) * (1.0f / 250.0f);
    }
    g_cat[b * 256 + tid] = outv;
}

// ---------------------------------------------------------------------------
// Kernel 2: mean0 = cat @ W1; out = sigmoid([h0 | mean0] @ W0 + b0).
// 128 blocks x 8 batch rows. 128 threads: thread = output dim d.
// ---------------------------------------------------------------------------
#define ROWS_PER_BLK 8

__global__ __launch_bounds__(128) void mlp_kernel(
    const float* __restrict__ embed,
    const float* __restrict__ W0,
    const float* __restrict__ b0,
    const float* __restrict__ W1,
    const int*   __restrict__ roots,
    float*       __restrict__ out)
{
    __shared__ __align__(16) float sCat[ROWS_PER_BLK * 256];

    const int d    = threadIdx.x;
    const int row0 = blockIdx.x * ROWS_PER_BLK;

    // Stage the 8 concat vectors
    for (int i = d; i < ROWS_PER_BLK * 256; i += 128)
        sCat[i] = g_cat[row0 * 256 + i];
    __syncthreads();

    // mean0[r][d] = sum_k cat[r][k] * W1[k][d]
    float acc[ROWS_PER_BLK];
#pragma unroll
    for (int r = 0; r < ROWS_PER_BLK; r++) acc[r] = 0.f;

    for (int k = 0; k < 256; k += 4) {
        const float w0 = __ldg(&W1[(k    ) * 128 + d]);
        const float w1 = __ldg(&W1[(k + 1) * 128 + d]);
        const float w2 = __ldg(&W1[(k + 2) * 128 + d]);
        const float w3 = __ldg(&W1[(k + 3) * 128 + d]);
#pragma unroll
        for (int r = 0; r < ROWS_PER_BLK; r++) {
            const float4 c = *(const float4*)&sCat[r * 256 + k];
            acc[r] = fmaf(c.x, w0, acc[r]);
            acc[r] = fmaf(c.y, w1, acc[r]);
            acc[r] = fmaf(c.z, w2, acc[r]);
            acc[r] = fmaf(c.w, w3, acc[r]);
        }
    }
    __syncthreads();

    // Build second concat: [h0 (root embedding) | mean0]
#pragma unroll
    for (int r = 0; r < ROWS_PER_BLK; r++) {
        const int root = __ldg(&roots[row0 + r]);
        sCat[r * 256 + d]       = __ldg(&embed[(size_t)root * DIM + d]);
        sCat[r * 256 + 128 + d] = acc[r];
    }
    __syncthreads();

    float acc2[ROWS_PER_BLK];
#pragma unroll
    for (int r = 0; r < ROWS_PER_BLK; r++) acc2[r] = 0.f;

    for (int k = 0; k < 256; k += 4) {
        const float w0 = __ldg(&W0[(k    ) * 128 + d]);
        const float w1 = __ldg(&W0[(k + 1) * 128 + d]);
        const float w2 = __ldg(&W0[(k + 2) * 128 + d]);
        const float w3 = __ldg(&W0[(k + 3) * 128 + d]);
#pragma unroll
        for (int r = 0; r < ROWS_PER_BLK; r++) {
            const float4 c = *(const float4*)&sCat[r * 256 + k];
            acc2[r] = fmaf(c.x, w0, acc2[r]);
            acc2[r] = fmaf(c.y, w1, acc2[r]);
            acc2[r] = fmaf(c.z, w2, acc2[r]);
            acc2[r] = fmaf(c.w, w3, acc2[r]);
        }
    }

    const float bb = __ldg(&b0[d]);
#pragma unroll
    for (int r = 0; r < ROWS_PER_BLK; r++) {
        const float x = acc2[r] + bb;
        out[(size_t)(row0 + r) * 128 + d] = 1.0f / (1.0f + __expf(-x));
    }
}

// ---------------------------------------------------------------------------
// Inputs (metadata order): embed_table, W0, b0, W1, roots, idx1, idx2
// ---------------------------------------------------------------------------
extern "C" void kernel_launch(void* const* d_in, const int* in_sizes, int n_in,
                              void* d_out, int out_size)
{
    const float* embed = (const float*)d_in[0];
    const float* W0    = (const float*)d_in[1];
    const float* b0    = (const float*)d_in[2];
    const float* W1    = (const float*)d_in[3];
    const int*   roots = (const int*)  d_in[4];
    const int*   idx1  = (const int*)  d_in[5];
    const int*   idx2  = (const int*)  d_in[6];
    float*       out   = (float*)d_out;

    gather_reduce_kernel<<<BATCH, 256>>>(embed, idx1, idx2);
    mlp_kernel<<<BATCH / ROWS_PER_BLK, 128>>>(embed, W0, b0, W1, roots, out);
}

// round 2
// speedup vs baseline: 1.6712x; 1.6712x over previous
#include <cuda_runtime.h>
#include <math.h>

#define BATCH 1024
#define DIM   128
#define N0    25
#define N1    10
#define NPB   250   // N0*N1 leaf rows per batch element

// Scratch (allocation-free __device__ globals):
// g_act[b][0:128)   = h0 (root embedding)
// g_act[b][128:256) = mean of idx1 embeddings
// g_act[b][256:384) = mean of idx2 (leaf) embeddings
__device__ float g_act[BATCH * 384];
// Fused weight: rows 0..127 = W0[0:128,:], rows 128..383 = W1 @ W0[128:256,:]
__device__ float g_Wf[384 * 128];

// ---------------------------------------------------------------------------
// Kernel 0: build fused weight. grid=384, block=128.
// ---------------------------------------------------------------------------
__global__ __launch_bounds__(128) void fuse_weights_kernel(
    const float* __restrict__ W0,
    const float* __restrict__ W1)
{
    const int k = blockIdx.x;
    const int d = threadIdx.x;

    if (k < 128) {                        // copy W0a rows
        g_Wf[k * 128 + d] = W0[k * 128 + d];
        return;
    }
    const int kk = k - 128;               // product rows: W1[kk,:] @ W0b
    __shared__ float a[128];
    a[d] = W1[kk * 128 + d];
    __syncthreads();

    float acc = 0.f;
#pragma unroll 8
    for (int j = 0; j < 128; j++)
        acc = fmaf(a[j], __ldg(&W0[(size_t)(128 + j) * 128 + d]), acc);
    g_Wf[k * 128 + d] = acc;
}

// ---------------------------------------------------------------------------
// Kernel 1: gather + reduce + root gather. One block per batch element.
// 256 threads: d = tid&127 (dim), g = tid>>7 (row-split group).
// ---------------------------------------------------------------------------
__global__ __launch_bounds__(256) void gather_reduce_kernel(
    const float* __restrict__ embed,
    const int*   __restrict__ roots,
    const int*   __restrict__ idx1,
    const int*   __restrict__ idx2)
{
    __shared__ int   sIdx2[NPB];
    __shared__ int   sIdx1[N0];
    __shared__ float red[512];
    __shared__ float sH0[128];

    const int b   = blockIdx.x;
    const int tid = threadIdx.x;
    const int d   = tid & 127;
    const int g   = tid >> 7;

    if (tid < NPB) sIdx2[tid] = idx2[b * NPB + tid];
    if (tid < N0)  sIdx1[tid] = idx1[b * N0 + tid];
    __syncthreads();

    const float* E = embed + d;

    // Sum of 125 leaf rows per group (5-wide MLP)
    float acc2 = 0.f;
    const int base = g * 125;
    for (int r = 0; r < 125; r += 5) {
        float v0 = __ldg(E + (size_t)sIdx2[base + r    ] * DIM);
        float v1 = __ldg(E + (size_t)sIdx2[base + r + 1] * DIM);
        float v2 = __ldg(E + (size_t)sIdx2[base + r + 2] * DIM);
        float v3 = __ldg(E + (size_t)sIdx2[base + r + 3] * DIM);
        float v4 = __ldg(E + (size_t)sIdx2[base + r + 4] * DIM);
        acc2 += (v0 + v1) + (v2 + v3) + v4;
    }

    // First-hop rows split by parity; group 1 also fetches the root embedding
    float acc1 = 0.f;
    for (int r = g; r < N0; r += 2)
        acc1 += __ldg(E + (size_t)sIdx1[r] * DIM);
    if (g == 1)
        sH0[d] = __ldg(&embed[(size_t)__ldg(&roots[b]) * DIM + d]);

    red[tid]       = acc2;
    red[256 + tid] = acc1;
    __syncthreads();

    float* A = g_act + b * 384;
    if (tid < 128) {
        A[tid]       = sH0[tid];                                      // h0
        A[128 + tid] = (red[256 + tid] + red[384 + tid]) * (1.f / 25.f);  // mean idx1
    } else {
        const int dd = tid - 128;
        A[256 + dd]  = (red[dd] + red[128 + dd]) * (1.f / 250.f);     // mean leaf
    }
}

// ---------------------------------------------------------------------------
// Kernel 2: out = sigmoid(g_act @ g_Wf + b0).
// grid=128, block=512. 8 rows/block. d = tid&127, kg = tid>>7 (4 k-groups of 96).
// ---------------------------------------------------------------------------
#define RPB 8

__global__ __launch_bounds__(512) void mlp_kernel(
    const float* __restrict__ b0,
    float*       __restrict__ out)
{
    __shared__ __align__(16) float sAct[RPB * 384];   // 12 KB
    __shared__ float red[4 * RPB * 128];               // 16 KB

    const int tid  = threadIdx.x;
    const int d    = tid & 127;
    const int kg   = tid >> 7;
    const int row0 = blockIdx.x * RPB;

    for (int i = tid; i < RPB * 384; i += 512)
        sAct[i] = g_act[row0 * 384 + i];
    __syncthreads();

    float acc[RPB];
#pragma unroll
    for (int r = 0; r < RPB; r++) acc[r] = 0.f;

    const int kbeg = kg * 96;
#pragma unroll 4
    for (int k = kbeg; k < kbeg + 96; k++) {
        const float w = __ldg(&g_Wf[(size_t)k * 128 + d]);
#pragma unroll
        for (int r = 0; r < RPB; r++)
            acc[r] = fmaf(sAct[r * 384 + k], w, acc[r]);
    }

    // red[kg][r][d]
#pragma unroll
    for (int r = 0; r < RPB; r++)
        red[kg * (RPB * 128) + r * 128 + d] = acc[r];
    __syncthreads();

    if (kg == 0) {
        const float bb = __ldg(&b0[d]);
#pragma unroll
        for (int r = 0; r < RPB; r++) {
            float s = red[0 * (RPB * 128) + r * 128 + d]
                    + red[1 * (RPB * 128) + r * 128 + d]
                    + red[2 * (RPB * 128) + r * 128 + d]
                    + red[3 * (RPB * 128) + r * 128 + d] + bb;
            out[(size_t)(row0 + r) * 128 + d] = 1.0f / (1.0f + __expf(-s));
        }
    }
}

// ---------------------------------------------------------------------------
// Inputs (metadata order): embed_table, W0, b0, W1, roots, idx1, idx2
// ---------------------------------------------------------------------------
extern "C" void kernel_launch(void* const* d_in, const int* in_sizes, int n_in,
                              void* d_out, int out_size)
{
    const float* embed = (const float*)d_in[0];
    const float* W0    = (const float*)d_in[1];
    const float* b0    = (const float*)d_in[2];
    const float* W1    = (const float*)d_in[3];
    const int*   roots = (const int*)  d_in[4];
    const int*   idx1  = (const int*)  d_in[5];
    const int*   idx2  = (const int*)  d_in[6];
    float*       out   = (float*)d_out;

    fuse_weights_kernel<<<384, 128>>>(W0, W1);
    gather_reduce_kernel<<<BATCH, 256>>>(embed, roots, idx1, idx2);
    mlp_kernel<<<BATCH / RPB, 512>>>(b0, out);
}

// round 4
// speedup vs baseline: 2.0021x; 1.1980x over previous
#include <cuda_runtime.h>
#include <math.h>

#define BATCH 1024
#define DIM   128
#define N0    25
#define N1    10
#define NPB   250
#define FUSE_BLOCKS 32          // 32 blocks x 8 rows = 256 product rows

// g_act[b][0:128)=h0, [128:256)=mean idx1, [256:384)=mean leaf
__device__ __align__(16) float g_act[BATCH * 384];
// g_Wf rows 0..127 = W0a ; rows 128..383 = W1 @ W0b
__device__ __align__(16) float g_Wf[384 * 128];

// ---------------------------------------------------------------------------
// Kernel A: blocks 0..1023 gather+reduce; blocks 1024.. build fused weights.
// 256 threads.
// ---------------------------------------------------------------------------
__global__ __launch_bounds__(256) void gather_fuse_kernel(
    const float* __restrict__ embed,
    const float* __restrict__ W0,
    const float* __restrict__ W1,
    const int*   __restrict__ roots,
    const int*   __restrict__ idx1,
    const int*   __restrict__ idx2)
{
    __shared__ int   sIdx2[NPB];
    __shared__ int   sIdx1[N0];
    __shared__ __align__(16) float sRedA[8 * 128];     // leaf partials per warp
    __shared__ __align__(16) float sRedB[8 * 128];     // idx1 partials per warp
    __shared__ __align__(16) float sW1[8 * 128];       // fuse: 8 W1 rows
    __shared__ __align__(16) float sRedF[2 * 8 * 128]; // fuse: j-group partials

    const int tid = threadIdx.x;

    if (blockIdx.x < BATCH) {
        // ------------------ gather path ------------------
        const int b = blockIdx.x;
        const int w = tid >> 5;          // warp 0..7
        const int l = tid & 31;          // lane
        const int e = l * 4;             // float4 element offset in row

        if (tid < NPB) sIdx2[tid] = idx2[b * NPB + tid];
        if (tid < N0)  sIdx1[tid] = idx1[b * N0 + tid];
        __syncthreads();

        const float* E = embed + e;

        // leaf rows: warp w handles r = w, w+8, ... (batches of 4 for MLP)
        float4 a2 = make_float4(0.f, 0.f, 0.f, 0.f);
        int r = w;
        for (; r + 24 < NPB; r += 32) {
            const float4 v0 = *(const float4*)(E + (size_t)sIdx2[r     ] * DIM);
            const float4 v1 = *(const float4*)(E + (size_t)sIdx2[r +  8] * DIM);
            const float4 v2 = *(const float4*)(E + (size_t)sIdx2[r + 16] * DIM);
            const float4 v3 = *(const float4*)(E + (size_t)sIdx2[r + 24] * DIM);
            a2.x += (v0.x + v1.x) + (v2.x + v3.x);
            a2.y += (v0.y + v1.y) + (v2.y + v3.y);
            a2.z += (v0.z + v1.z) + (v2.z + v3.z);
            a2.w += (v0.w + v1.w) + (v2.w + v3.w);
        }
        for (; r < NPB; r += 8) {
            const float4 v = *(const float4*)(E + (size_t)sIdx2[r] * DIM);
            a2.x += v.x; a2.y += v.y; a2.z += v.z; a2.w += v.w;
        }

        // idx1 rows
        float4 a1 = make_float4(0.f, 0.f, 0.f, 0.f);
        for (int q = w; q < N0; q += 8) {
            const float4 v = *(const float4*)(E + (size_t)sIdx1[q] * DIM);
            a1.x += v.x; a1.y += v.y; a1.z += v.z; a1.w += v.w;
        }

        // root embedding: warp 0 writes straight through
        if (w == 0) {
            const float4 h0 = *(const float4*)(E + (size_t)__ldg(&roots[b]) * DIM);
            *(float4*)&g_act[b * 384 + e] = h0;
        }

        *(float4*)&sRedA[w * 128 + e] = a2;
        *(float4*)&sRedB[w * 128 + e] = a1;
        __syncthreads();

        if (tid < 128) {
            float s = 0.f;
#pragma unroll
            for (int j = 0; j < 8; j++) s += sRedB[j * 128 + tid];
            g_act[b * 384 + 128 + tid] = s * (1.0f / 25.0f);
        } else {
            const int dd = tid - 128;
            float s = 0.f;
#pragma unroll
            for (int j = 0; j < 8; j++) s += sRedA[j * 128 + dd];
            g_act[b * 384 + 256 + dd] = s * (1.0f / 250.0f);
        }
    } else {
        // ------------------ fuse path ------------------
        const int fb  = blockIdx.x - BATCH;      // 0..31
        const int kk0 = fb * 8;

        // copy W0a rows [fb*4, fb*4+4)
        {
            const int base = fb * 512;
#pragma unroll
            for (int i = 0; i < 2; i++)
                g_Wf[base + tid + i * 256] = __ldg(&W0[base + tid + i * 256]);
        }

        // stage 8 rows of W1
        for (int i = tid; i < 1024; i += 256)
            sW1[i] = __ldg(&W1[kk0 * 128 + i]);
        __syncthreads();

        const int g = tid >> 7;      // j-group 0/1 (64 j each)
        const int d = tid & 127;

        float acc[8];
#pragma unroll
        for (int rr = 0; rr < 8; rr++) acc[rr] = 0.f;

        const int jbeg = g * 64;
        for (int j = 0; j < 64; j += 4) {
            float wv[4];
#pragma unroll
            for (int u = 0; u < 4; u++)
                wv[u] = __ldg(&W0[(size_t)(128 + jbeg + j + u) * 128 + d]);
#pragma unroll
            for (int u = 0; u < 4; u++) {
#pragma unroll
                for (int rr = 0; rr < 8; rr++)
                    acc[rr] = fmaf(sW1[rr * 128 + jbeg + j + u], wv[u], acc[rr]);
            }
        }

#pragma unroll
        for (int rr = 0; rr < 8; rr++)
            sRedF[g * 1024 + rr * 128 + d] = acc[rr];
        __syncthreads();

        if (g == 0) {
#pragma unroll
            for (int rr = 0; rr < 8; rr++)
                g_Wf[(size_t)(128 + kk0 + rr) * 128 + d] =
                    sRedF[rr * 128 + d] + sRedF[1024 + rr * 128 + d];
        }
    }
}

// ---------------------------------------------------------------------------
// Kernel B: out = sigmoid(g_act @ g_Wf + b0). grid=128, block=512, 8 rows/blk.
// d = tid&127, kg = tid>>7 (4 k-groups of 96). Activations transposed in smem.
// ---------------------------------------------------------------------------
__global__ __launch_bounds__(512) void mlp_kernel(
    const float* __restrict__ b0,
    float*       __restrict__ out)
{
    __shared__ __align__(16) float sActT[384 * 8];   // [k][r], 12 KB
    __shared__ __align__(16) float sRed[4 * 8 * 128]; // 16 KB

    const int tid  = threadIdx.x;
    const int d    = tid & 127;
    const int kg   = tid >> 7;
    const int row0 = blockIdx.x * 8;

    // stage transposed activations
    for (int i = tid; i < 8 * 384; i += 512) {
        const int r = i / 384;
        const int k = i - r * 384;
        sActT[k * 8 + r] = g_act[(size_t)(row0 + r) * 384 + k];
    }
    __syncthreads();

    float acc[8];
#pragma unroll
    for (int r = 0; r < 8; r++) acc[r] = 0.f;

    const int kbeg = kg * 96;
    for (int k = 0; k < 96; k += 8) {
        float wv[8];
#pragma unroll
        for (int u = 0; u < 8; u++)
            wv[u] = __ldg(&g_Wf[(size_t)(kbeg + k + u) * 128 + d]);
#pragma unroll
        for (int u = 0; u < 8; u++) {
            const float4 aLo = *(const float4*)&sActT[(kbeg + k + u) * 8];
            const float4 aHi = *(const float4*)&sActT[(kbeg + k + u) * 8 + 4];
            acc[0] = fmaf(aLo.x, wv[u], acc[0]);
            acc[1] = fmaf(aLo.y, wv[u], acc[1]);
            acc[2] = fmaf(aLo.z, wv[u], acc[2]);
            acc[3] = fmaf(aLo.w, wv[u], acc[3]);
            acc[4] = fmaf(aHi.x, wv[u], acc[4]);
            acc[5] = fmaf(aHi.y, wv[u], acc[5]);
            acc[6] = fmaf(aHi.z, wv[u], acc[6]);
            acc[7] = fmaf(aHi.w, wv[u], acc[7]);
        }
    }

#pragma unroll
    for (int r = 0; r < 8; r++)
        sRed[kg * 1024 + r * 128 + d] = acc[r];
    __syncthreads();

    if (kg == 0) {
        const float bb = __ldg(&b0[d]);
#pragma unroll
        for (int r = 0; r < 8; r++) {
            const float s = sRed[r * 128 + d] + sRed[1024 + r * 128 + d]
                          + sRed[2048 + r * 128 + d] + sRed[3072 + r * 128 + d] + bb;
            out[(size_t)(row0 + r) * 128 + d] = 1.0f / (1.0f + __expf(-s));
        }
    }
}

// ---------------------------------------------------------------------------
// Inputs: embed_table, W0, b0, W1, roots, idx1, idx2
// ---------------------------------------------------------------------------
extern "C" void kernel_launch(void* const* d_in, const int* in_sizes, int n_in,
                              void* d_out, int out_size)
{
    const float* embed = (const float*)d_in[0];
    const float* W0    = (const float*)d_in[1];
    const float* b0    = (const float*)d_in[2];
    const float* W1    = (const float*)d_in[3];
    const int*   roots = (const int*)  d_in[4];
    const int*   idx1  = (const int*)  d_in[5];
    const int*   idx2  = (const int*)  d_in[6];
    float*       out   = (float*)d_out;

    gather_fuse_kernel<<<BATCH + FUSE_BLOCKS, 256>>>(embed, W0, W1, roots, idx1, idx2);
    mlp_kernel<<<BATCH / 8, 512>>>(b0, out);
}